// round 16
// baseline (speedup 1.0000x reference)
#include <cuda_runtime.h>
#include <math.h>

#define NMAX 100000
#define EMAX 3200000
#define NEG 0.2f

// ---------------- scratch (device globals; no allocations) ----------------
__device__ float4 g_xl1[NMAX * 4];   // [N,4,4] layer1 left proj
__device__ float4 g_xr1[NMAX * 4];   // [N,4,4] layer1 right proj
__device__ float4 g_acc1[NMAX * 4];  // softmax numerator accum
__device__ float4 g_den1[NMAX];      // softmax denominator, 4 heads packed
__device__ float4 g_xl2[NMAX * 8];   // [N,4,8]
__device__ float4 g_xr2[NMAX * 8];
__device__ float4 g_acc2[NMAX * 8];
__device__ float4 g_den2[NMAX];      // 4 heads packed
__device__ float4 g_lc[NMAX];        // {sum ew, sum ce, in-degree, pad} per dst
__device__ float2 g_ps[NMAX];        // h_final . W[2:34]
__device__ float2 g_pd[NMAX];        // h_final . W[34:66]
__device__ float  g_W[132];          // collapsed edge MLP weights [66,2]
__device__ float  g_Wb[2];           // collapsed bias
__device__ __align__(16) float g_Wp[128]; // packed {Ws0,Ws1,Wd0,Wd1} per k=0..31
__device__ float4 g_ep[EMAX];        // packed {s_bits, d_bits, w, c} per edge

__device__ __forceinline__ float lrelu(float x) { return x > 0.f ? x : NEG * x; }
__device__ __forceinline__ float4 ldg4(const float* p) { return __ldg((const float4*)p); }
__device__ __forceinline__ void fma4(float4& a, float s, float4 w) {
    a.x += s * w.x; a.y += s * w.y; a.z += s * w.z; a.w += s * w.w;
}
__device__ __forceinline__ float4 lrelu4(float4 m) {
    return make_float4(lrelu(m.x), lrelu(m.y), lrelu(m.z), lrelu(m.w));
}
__device__ __forceinline__ float dot4(float4 a, float4 b) {
    return a.x * b.x + a.y * b.y + a.z * b.z + a.w * b.w;
}

__device__ __forceinline__ void redAdd4(float4* p, float4 v) {
    asm volatile("red.global.add.v4.f32 [%0], {%1,%2,%3,%4};"
                 :: "l"(p), "f"(v.x), "f"(v.y), "f"(v.z), "f"(v.w) : "memory");
}

// ---------------- node: zero accum + init MLP + layer1 proj + MLP collapse -
__global__ void __launch_bounds__(128, 6) k_nodes1(
    const float* __restrict__ x,
    const float* __restrict__ w_init, const float* __restrict__ b_init,
    const float* __restrict__ w1l, const float* __restrict__ b1l,
    const float* __restrict__ w1r, const float* __restrict__ b1r,
    const float* __restrict__ we1, const float* __restrict__ be1,
    const float* __restrict__ we2, const float* __restrict__ be2, int N)
{
    // block 0: collapse edge MLP (consumed only by k_selfnorm2 / k_edgeout)
    if (blockIdx.x == 0) {
        int i = threadIdx.x;
        if (i < 66) {
            float a = 0.f, b = 0.f;
#pragma unroll
            for (int k = 0; k < 32; k++) {
                float w = __ldg(&we1[i * 32 + k]);
                a += w * __ldg(&we2[k * 2 + 0]);
                b += w * __ldg(&we2[k * 2 + 1]);
            }
            g_W[i * 2 + 0] = a;
            g_W[i * 2 + 1] = b;
            if (i >= 2 && i < 34) {
                g_Wp[(i - 2) * 4 + 0] = a;
                g_Wp[(i - 2) * 4 + 1] = b;
            } else if (i >= 34) {
                g_Wp[(i - 34) * 4 + 2] = a;
                g_Wp[(i - 34) * 4 + 3] = b;
            }
        } else if (i == 66) {
            float a = __ldg(&be2[0]), b = __ldg(&be2[1]);
            for (int k = 0; k < 32; k++) {
                a += __ldg(&be1[k]) * __ldg(&we2[k * 2 + 0]);
                b += __ldg(&be1[k]) * __ldg(&we2[k * 2 + 1]);
            }
            g_Wb[0] = a; g_Wb[1] = b;
        }
    }

    int n = blockIdx.x * blockDim.x + threadIdx.x;
    if (n >= N) return;

    float4 z4 = make_float4(0.f, 0.f, 0.f, 0.f);
    g_lc[n] = z4;
    g_den1[n] = z4;
    g_den2[n] = z4;
#pragma unroll
    for (int q = 0; q < 4; q++) g_acc1[n * 4 + q] = z4;
#pragma unroll
    for (int q = 0; q < 8; q++) g_acc2[n * 8 + q] = z4;

    float xi[5];
#pragma unroll
    for (int i = 0; i < 5; i++) xi[i] = x[n * 5 + i];

    float4 a0 = ldg4(b_init), a1 = ldg4(b_init + 4);
#pragma unroll
    for (int i = 0; i < 5; i++) {
        fma4(a0, xi[i], ldg4(w_init + i * 8));
        fma4(a1, xi[i], ldg4(w_init + i * 8 + 4));
    }
    float h0[8] = {fmaxf(a0.x, 0.f), fmaxf(a0.y, 0.f), fmaxf(a0.z, 0.f), fmaxf(a0.w, 0.f),
                   fmaxf(a1.x, 0.f), fmaxf(a1.y, 0.f), fmaxf(a1.z, 0.f), fmaxf(a1.w, 0.f)};

    {
        float4 v[4];
#pragma unroll
        for (int q = 0; q < 4; q++) v[q] = ldg4(b1l + q * 4);
#pragma unroll
        for (int i = 0; i < 8; i++) {
            float s = h0[i];
#pragma unroll
            for (int q = 0; q < 4; q++) fma4(v[q], s, ldg4(w1l + i * 16 + q * 4));
        }
#pragma unroll
        for (int q = 0; q < 4; q++) g_xl1[n * 4 + q] = v[q];
    }
    {
        float4 v[4];
#pragma unroll
        for (int q = 0; q < 4; q++) v[q] = ldg4(b1r + q * 4);
#pragma unroll
        for (int i = 0; i < 8; i++) {
            float s = h0[i];
#pragma unroll
            for (int q = 0; q < 4; q++) fma4(v[q], s, ldg4(w1r + i * 16 + q * 4));
        }
#pragma unroll
        for (int q = 0; q < 4; q++) g_xr1[n * 4 + q] = v[q];
    }
}

// ---------------- edge pass, layer 1 (4 threads/edge; packs edge data) -----
__global__ void k_edge1(const int* __restrict__ ei, const float* __restrict__ ew,
                        const float* __restrict__ ce,
                        const float* __restrict__ w1e, const float* __restrict__ att1,
                        int E) {
    __shared__ __align__(16) float s_w1e[32];
    __shared__ __align__(16) float s_att1[16];
    if (threadIdx.x < 32) s_w1e[threadIdx.x] = __ldg(&w1e[threadIdx.x]);
    if (threadIdx.x < 16) s_att1[threadIdx.x] = __ldg(&att1[threadIdx.x]);
    __syncthreads();

    int t = blockIdx.x * blockDim.x + threadIdx.x;
    int e = t >> 2, h = t & 3;
    bool valid = (e < E);
    int ec = valid ? e : (E - 1);
    int s = __ldg(ei + ec);
    int d = __ldg(ei + (size_t)E + ec);
    float w = __ldg(ew + ec), c = __ldg(ce + ec);
    if (valid && h == 0) {
        g_ep[e] = make_float4(__int_as_float(s), __int_as_float(d), w, c);
        redAdd4(&g_lc[d], make_float4(w, c, 1.f, 0.f));
    }
    float4 xl = __ldg(&g_xl1[s * 4 + h]);
    float4 xr = __ldg(&g_xr1[d * 4 + h]);
    float4 wa = *(const float4*)&s_w1e[h * 4];
    float4 wb = *(const float4*)&s_w1e[16 + h * 4];
    float4 at = *(const float4*)&s_att1[h * 4];
    float4 m;
    m.x = xl.x + xr.x + w * wa.x + c * wb.x;
    m.y = xl.y + xr.y + w * wa.y + c * wb.y;
    m.z = xl.z + xr.z + w * wa.z + c * wb.z;
    m.w = xl.w + xr.w + w * wa.w + c * wb.w;
    float al = dot4(lrelu4(m), at);
    float ex = __expf(al);
    // pack den: lead lane (h==0) of each 4-lane edge group assembles float4
    float e1 = __shfl_down_sync(0xffffffffu, ex, 1);
    float e2 = __shfl_down_sync(0xffffffffu, ex, 2);
    float e3 = __shfl_down_sync(0xffffffffu, ex, 3);
    if (valid) {
        redAdd4(&g_acc1[d * 4 + h], make_float4(ex * xl.x, ex * xl.y, ex * xl.z, ex * xl.w));
        if (h == 0) redAdd4(&g_den1[d], make_float4(ex, e1, e2, e3));
    }
}

// ---------------- node: self-loop + normalize layer1 + layer2 projections --
__global__ void __launch_bounds__(128, 6) k_selfnorm1(
    const float* __restrict__ w1e, const float* __restrict__ att1,
    const float* __restrict__ bias1,
    const float* __restrict__ w2l, const float* __restrict__ b2l,
    const float* __restrict__ w2r, const float* __restrict__ b2r, int N)
{
    int n = blockIdx.x * blockDim.x + threadIdx.x;
    if (n >= N) return;
    float4 lc = g_lc[n];
    float icnt = __fdividef(1.f, fmaxf(lc.z, 1.f));
    float la0 = lc.x * icnt, la1 = lc.y * icnt;
    float4 den4 = g_den1[n];
    float dv[4] = {den4.x, den4.y, den4.z, den4.w};
    float h1[16];
#pragma unroll
    for (int h = 0; h < 4; h++) {
        float4 xl = g_xl1[n * 4 + h];
        float4 xr = g_xr1[n * 4 + h];
        float4 wa = ldg4(&w1e[h * 4]);
        float4 wb = ldg4(&w1e[16 + h * 4]);
        float4 at = ldg4(&att1[h * 4]);
        float4 m;
        m.x = xl.x + xr.x + la0 * wa.x + la1 * wb.x;
        m.y = xl.y + xr.y + la0 * wa.y + la1 * wb.y;
        m.z = xl.z + xr.z + la0 * wa.z + la1 * wb.z;
        m.w = xl.w + xr.w + la0 * wa.w + la1 * wb.w;
        float ex = __expf(dot4(lrelu4(m), at));
        float iden = __fdividef(1.f, dv[h] + ex);
        float4 ac = g_acc1[n * 4 + h];
        float4 bi = ldg4(&bias1[h * 4]);
        h1[h * 4 + 0] = fmaxf((ac.x + ex * xl.x) * iden + bi.x, 0.f);
        h1[h * 4 + 1] = fmaxf((ac.y + ex * xl.y) * iden + bi.y, 0.f);
        h1[h * 4 + 2] = fmaxf((ac.z + ex * xl.z) * iden + bi.z, 0.f);
        h1[h * 4 + 3] = fmaxf((ac.w + ex * xl.w) * iden + bi.w, 0.f);
    }
    {
        float4 v[8];
#pragma unroll
        for (int q = 0; q < 8; q++) v[q] = ldg4(b2l + q * 4);
#pragma unroll
        for (int i = 0; i < 16; i++) {
            float s = h1[i];
#pragma unroll
            for (int q = 0; q < 8; q++) fma4(v[q], s, ldg4(w2l + i * 32 + q * 4));
        }
#pragma unroll
        for (int q = 0; q < 8; q++) g_xl2[n * 8 + q] = v[q];
    }
    {
        float4 v[8];
#pragma unroll
        for (int q = 0; q < 8; q++) v[q] = ldg4(b2r + q * 4);
#pragma unroll
        for (int i = 0; i < 16; i++) {
            float s = h1[i];
#pragma unroll
            for (int q = 0; q < 8; q++) fma4(v[q], s, ldg4(w2r + i * 32 + q * 4));
        }
#pragma unroll
        for (int q = 0; q < 8; q++) g_xr2[n * 8 + q] = v[q];
    }
}

// ---------------- edge pass, layer 2 (8 threads/edge; packed edge data) ----
__global__ void k_edge2(const float* __restrict__ w2e, const float* __restrict__ att2,
                        int E) {
    __shared__ __align__(16) float s_w2e[64];
    __shared__ __align__(16) float s_att2[32];
    if (threadIdx.x < 64) s_w2e[threadIdx.x] = __ldg(&w2e[threadIdx.x]);
    if (threadIdx.x < 32) s_att2[threadIdx.x] = __ldg(&att2[threadIdx.x]);
    __syncthreads();

    long long t = (long long)blockIdx.x * blockDim.x + threadIdx.x;
    int e = (int)(t >> 3);
    int sub = (int)(t & 7);
    int h = sub >> 1, half = sub & 1;
    bool valid = (e < E);
    int ec = valid ? e : (E - 1);
    float4 ep = __ldg(&g_ep[ec]);
    int s = __float_as_int(ep.x);
    int d = __float_as_int(ep.y);
    float w = ep.z, c = ep.w;

    float4 a = __ldg(&g_xl2[s * 8 + h * 2 + half]);
    float4 b = __ldg(&g_xr2[d * 8 + h * 2 + half]);
    float4 wa = *(const float4*)&s_w2e[h * 8 + half * 4];
    float4 wb = *(const float4*)&s_w2e[32 + h * 8 + half * 4];
    float4 at = *(const float4*)&s_att2[h * 8 + half * 4];
    float4 m;
    m.x = a.x + b.x + w * wa.x + c * wb.x;
    m.y = a.y + b.y + w * wa.y + c * wb.y;
    m.z = a.z + b.z + w * wa.z + c * wb.z;
    m.w = a.w + b.w + w * wa.w + c * wb.w;
    float part = dot4(lrelu4(m), at);
    float al = part + __shfl_xor_sync(0xffffffffu, part, 1);
    float ex = __expf(al);
    // pack den: sub==0 lane assembles (ex_h0, ex_h1, ex_h2, ex_h3)
    float e1 = __shfl_down_sync(0xffffffffu, ex, 2);
    float e2 = __shfl_down_sync(0xffffffffu, ex, 4);
    float e3 = __shfl_down_sync(0xffffffffu, ex, 6);
    if (valid) {
        redAdd4(&g_acc2[d * 8 + h * 2 + half],
                make_float4(ex * a.x, ex * a.y, ex * a.z, ex * a.w));
        if (sub == 0) redAdd4(&g_den2[d], make_float4(ex, e1, e2, e3));
    }
}

// ---------------- node: self-loop + normalize layer2 + FC + ps/pd ----------
__global__ void __launch_bounds__(128, 6) k_selfnorm2(
    const float* __restrict__ w2e, const float* __restrict__ att2,
    const float* __restrict__ bias2,
    const float* __restrict__ wfc, const float* __restrict__ bfc, int N)
{
    int n = blockIdx.x * blockDim.x + threadIdx.x;
    if (n >= N) return;
    float4 lc = g_lc[n];
    float icnt = __fdividef(1.f, fmaxf(lc.z, 1.f));
    float la0 = lc.x * icnt, la1 = lc.y * icnt;
    float4 den4 = g_den2[n];
    float dv[4] = {den4.x, den4.y, den4.z, den4.w};
    float h2[32];
#pragma unroll
    for (int h = 0; h < 4; h++) {
        float4 a0 = g_xl2[n * 8 + h * 2], a1 = g_xl2[n * 8 + h * 2 + 1];
        float4 b0 = g_xr2[n * 8 + h * 2], b1 = g_xr2[n * 8 + h * 2 + 1];
        float4 wa0 = ldg4(&w2e[h * 8]),      wa1 = ldg4(&w2e[h * 8 + 4]);
        float4 wb0 = ldg4(&w2e[32 + h * 8]), wb1 = ldg4(&w2e[32 + h * 8 + 4]);
        float4 at0 = ldg4(&att2[h * 8]),     at1 = ldg4(&att2[h * 8 + 4]);
        float4 m0, m1;
        m0.x = a0.x + b0.x + la0 * wa0.x + la1 * wb0.x;
        m0.y = a0.y + b0.y + la0 * wa0.y + la1 * wb0.y;
        m0.z = a0.z + b0.z + la0 * wa0.z + la1 * wb0.z;
        m0.w = a0.w + b0.w + la0 * wa0.w + la1 * wb0.w;
        m1.x = a1.x + b1.x + la0 * wa1.x + la1 * wb1.x;
        m1.y = a1.y + b1.y + la0 * wa1.y + la1 * wb1.y;
        m1.z = a1.z + b1.z + la0 * wa1.z + la1 * wb1.z;
        m1.w = a1.w + b1.w + la0 * wa1.w + la1 * wb1.w;
        float ex = __expf(dot4(lrelu4(m0), at0) + dot4(lrelu4(m1), at1));
        float iden = __fdividef(1.f, dv[h] + ex);
        float4 c0 = g_acc2[n * 8 + h * 2], c1 = g_acc2[n * 8 + h * 2 + 1];
        float4 bi0 = ldg4(&bias2[h * 8]), bi1 = ldg4(&bias2[h * 8 + 4]);
        h2[h * 8 + 0] = fmaxf((c0.x + ex * a0.x) * iden + bi0.x, 0.f);
        h2[h * 8 + 1] = fmaxf((c0.y + ex * a0.y) * iden + bi0.y, 0.f);
        h2[h * 8 + 2] = fmaxf((c0.z + ex * a0.z) * iden + bi0.z, 0.f);
        h2[h * 8 + 3] = fmaxf((c0.w + ex * a0.w) * iden + bi0.w, 0.f);
        h2[h * 8 + 4] = fmaxf((c1.x + ex * a1.x) * iden + bi1.x, 0.f);
        h2[h * 8 + 5] = fmaxf((c1.y + ex * a1.y) * iden + bi1.y, 0.f);
        h2[h * 8 + 6] = fmaxf((c1.z + ex * a1.z) * iden + bi1.z, 0.f);
        h2[h * 8 + 7] = fmaxf((c1.w + ex * a1.w) * iden + bi1.w, 0.f);
    }
    float p0 = 0.f, p1 = 0.f, q0 = 0.f, q1 = 0.f;
#pragma unroll
    for (int half = 0; half < 2; half++) {
        float4 acc[4];
#pragma unroll
        for (int q = 0; q < 4; q++) acc[q] = ldg4(bfc + half * 16 + q * 4);
#pragma unroll
        for (int i = 0; i < 32; i++) {
            float v = h2[i];
#pragma unroll
            for (int q = 0; q < 4; q++)
                fma4(acc[q], v, ldg4(wfc + i * 32 + half * 16 + q * 4));
        }
#pragma unroll
        for (int q = 0; q < 4; q++) {
            float hv[4] = {fmaxf(acc[q].x, 0.f), fmaxf(acc[q].y, 0.f),
                           fmaxf(acc[q].z, 0.f), fmaxf(acc[q].w, 0.f)};
#pragma unroll
            for (int cmp = 0; cmp < 4; cmp++) {
                int k = half * 16 + q * 4 + cmp;
                float4 wp = ldg4(&g_Wp[k * 4]);
                p0 += hv[cmp] * wp.x; p1 += hv[cmp] * wp.y;
                q0 += hv[cmp] * wp.z; q1 += hv[cmp] * wp.w;
            }
        }
    }
    g_ps[n] = make_float2(p0, p1);
    g_pd[n] = make_float2(q0, q1);
}

// ---------------- final edge output (packed edge data) ----------------
__global__ void k_edgeout(float* __restrict__ out, int E) {
    int e = blockIdx.x * blockDim.x + threadIdx.x;
    if (e >= E) return;
    float4 ep = __ldg(&g_ep[e]);
    int s = __float_as_int(ep.x);
    int d = __float_as_int(ep.y);
    float2 ps = __ldg(&g_ps[s]);
    float2 pd = __ldg(&g_pd[d]);
    float2 o;
    o.x = __ldg(&g_Wb[0]) + ep.z * __ldg(&g_W[0]) + ep.w * __ldg(&g_W[2]) + ps.x + pd.x;
    o.y = __ldg(&g_Wb[1]) + ep.z * __ldg(&g_W[1]) + ep.w * __ldg(&g_W[3]) + ps.y + pd.y;
    __stcs((float2*)out + e, o);   // streaming store: output never re-read
}

// ---------------- launch ----------------
extern "C" void kernel_launch(void* const* d_in, const int* in_sizes, int n_in,
                              void* d_out, int out_size) {
    const float* x  = (const float*)d_in[0];
    const int*   ei = (const int*)d_in[1];   // int32 [2,E]
    const float* ew = (const float*)d_in[2];
    const float* ce = (const float*)d_in[3];
    int N = in_sizes[0] / 5;
    int E = in_sizes[2];

    const float* w_init = (const float*)d_in[4];
    const float* b_init = (const float*)d_in[5];
    const float* w1l = (const float*)d_in[6];
    const float* b1l = (const float*)d_in[7];
    const float* w1r = (const float*)d_in[8];
    const float* b1r = (const float*)d_in[9];
    const float* w1e = (const float*)d_in[10];
    const float* att1 = (const float*)d_in[11];
    const float* bias1 = (const float*)d_in[12];
    const float* w2l = (const float*)d_in[13];
    const float* b2l = (const float*)d_in[14];
    const float* w2r = (const float*)d_in[15];
    const float* b2r = (const float*)d_in[16];
    const float* w2e = (const float*)d_in[17];
    const float* att2 = (const float*)d_in[18];
    const float* bias2 = (const float*)d_in[19];
    const float* wfc = (const float*)d_in[20];
    const float* bfc = (const float*)d_in[21];
    const float* we1 = (const float*)d_in[22];
    const float* be1 = (const float*)d_in[23];
    const float* we2 = (const float*)d_in[24];
    const float* be2 = (const float*)d_in[25];

    int nb = (N + 127) / 128;
    k_nodes1<<<nb, 128>>>(x, w_init, b_init, w1l, b1l, w1r, b1r,
                          we1, be1, we2, be2, N);

    long long tE4 = 4LL * E;
    int eb4 = (int)((tE4 + 255) / 256);
    k_edge1<<<eb4, 256>>>(ei, ew, ce, w1e, att1, E);
    k_selfnorm1<<<nb, 128>>>(w1e, att1, bias1, w2l, b2l, w2r, b2r, N);

    long long tE8 = 8LL * E;
    int eb8 = (int)((tE8 + 255) / 256);
    k_edge2<<<eb8, 256>>>(w2e, att2, E);
    k_selfnorm2<<<nb, 128>>>(w2e, att2, bias2, wfc, bfc, N);
    k_edgeout<<<(E + 255) / 256, 256>>>((float*)d_out, E);
}

// round 17
// speedup vs baseline: 1.0950x; 1.0950x over previous
#include <cuda_runtime.h>
#include <math.h>

#define NMAX 100000
#define EMAX 3200000
#define NEG 0.2f

// ---------------- scratch (device globals; no allocations) ----------------
__device__ float4 g_xl1[NMAX * 4];   // [N,4,4] layer1 left proj
__device__ float4 g_xr1[NMAX * 4];   // [N,4,4] layer1 right proj
__device__ float4 g_acc1[NMAX * 4];  // softmax numerator accum
__device__ float  g_den1[NMAX * 4];  // softmax denominator accum
__device__ float4 g_xl2[NMAX * 8];   // [N,4,8]
__device__ float4 g_xr2[NMAX * 8];
__device__ float4 g_acc2[NMAX * 8];
__device__ float  g_den2[NMAX * 4];
__device__ float4 g_lc[NMAX];        // {sum ew, sum ce, in-degree, pad} per dst
__device__ float2 g_ps[NMAX];        // h_final . W[2:34]
__device__ float2 g_pd[NMAX];        // h_final . W[34:66]
__device__ float  g_W[132];          // collapsed edge MLP weights [66,2]
__device__ float  g_Wb[2];           // collapsed bias
__device__ __align__(16) float g_Wp[128]; // packed {Ws0,Ws1,Wd0,Wd1} per k=0..31
__device__ float4 g_ep[EMAX];        // packed {s_bits, d_bits, w, c} per edge

__device__ __forceinline__ float lrelu(float x) { return x > 0.f ? x : NEG * x; }
__device__ __forceinline__ float4 ldg4(const float* p) { return __ldg((const float4*)p); }
__device__ __forceinline__ void fma4(float4& a, float s, float4 w) {
    a.x += s * w.x; a.y += s * w.y; a.z += s * w.z; a.w += s * w.w;
}
__device__ __forceinline__ float4 lrelu4(float4 m) {
    return make_float4(lrelu(m.x), lrelu(m.y), lrelu(m.z), lrelu(m.w));
}
__device__ __forceinline__ float dot4(float4 a, float4 b) {
    return a.x * b.x + a.y * b.y + a.z * b.z + a.w * b.w;
}

__device__ __forceinline__ void redAdd(float* p, float v) {
    asm volatile("red.global.add.f32 [%0], %1;" :: "l"(p), "f"(v) : "memory");
}
__device__ __forceinline__ void redAdd4(float4* p, float4 v) {
    asm volatile("red.global.add.v4.f32 [%0], {%1,%2,%3,%4};"
                 :: "l"(p), "f"(v.x), "f"(v.y), "f"(v.z), "f"(v.w) : "memory");
}

// ---------------- node: zero accum + init MLP + layer1 proj + MLP collapse -
__global__ void __launch_bounds__(128, 6) k_nodes1(
    const float* __restrict__ x,
    const float* __restrict__ w_init, const float* __restrict__ b_init,
    const float* __restrict__ w1l, const float* __restrict__ b1l,
    const float* __restrict__ w1r, const float* __restrict__ b1r,
    const float* __restrict__ we1, const float* __restrict__ be1,
    const float* __restrict__ we2, const float* __restrict__ be2, int N)
{
    // block 0: collapse edge MLP (consumed only by k_selfnorm2 / k_edgeout)
    if (blockIdx.x == 0) {
        int i = threadIdx.x;
        if (i < 66) {
            float a = 0.f, b = 0.f;
#pragma unroll
            for (int k = 0; k < 32; k++) {
                float w = __ldg(&we1[i * 32 + k]);
                a += w * __ldg(&we2[k * 2 + 0]);
                b += w * __ldg(&we2[k * 2 + 1]);
            }
            g_W[i * 2 + 0] = a;
            g_W[i * 2 + 1] = b;
            if (i >= 2 && i < 34) {
                g_Wp[(i - 2) * 4 + 0] = a;
                g_Wp[(i - 2) * 4 + 1] = b;
            } else if (i >= 34) {
                g_Wp[(i - 34) * 4 + 2] = a;
                g_Wp[(i - 34) * 4 + 3] = b;
            }
        } else if (i == 66) {
            float a = __ldg(&be2[0]), b = __ldg(&be2[1]);
            for (int k = 0; k < 32; k++) {
                a += __ldg(&be1[k]) * __ldg(&we2[k * 2 + 0]);
                b += __ldg(&be1[k]) * __ldg(&we2[k * 2 + 1]);
            }
            g_Wb[0] = a; g_Wb[1] = b;
        }
    }

    int n = blockIdx.x * blockDim.x + threadIdx.x;
    if (n >= N) return;

    float4 z4 = make_float4(0.f, 0.f, 0.f, 0.f);
    g_lc[n] = z4;
#pragma unroll
    for (int q = 0; q < 4; q++) {
        g_den1[n * 4 + q] = 0.f;
        g_den2[n * 4 + q] = 0.f;
        g_acc1[n * 4 + q] = z4;
    }
#pragma unroll
    for (int q = 0; q < 8; q++) g_acc2[n * 8 + q] = z4;

    float xi[5];
#pragma unroll
    for (int i = 0; i < 5; i++) xi[i] = x[n * 5 + i];

    float4 a0 = ldg4(b_init), a1 = ldg4(b_init + 4);
#pragma unroll
    for (int i = 0; i < 5; i++) {
        fma4(a0, xi[i], ldg4(w_init + i * 8));
        fma4(a1, xi[i], ldg4(w_init + i * 8 + 4));
    }
    float h0[8] = {fmaxf(a0.x, 0.f), fmaxf(a0.y, 0.f), fmaxf(a0.z, 0.f), fmaxf(a0.w, 0.f),
                   fmaxf(a1.x, 0.f), fmaxf(a1.y, 0.f), fmaxf(a1.z, 0.f), fmaxf(a1.w, 0.f)};

    {
        float4 v[4];
#pragma unroll
        for (int q = 0; q < 4; q++) v[q] = ldg4(b1l + q * 4);
#pragma unroll
        for (int i = 0; i < 8; i++) {
            float s = h0[i];
#pragma unroll
            for (int q = 0; q < 4; q++) fma4(v[q], s, ldg4(w1l + i * 16 + q * 4));
        }
#pragma unroll
        for (int q = 0; q < 4; q++) g_xl1[n * 4 + q] = v[q];
    }
    {
        float4 v[4];
#pragma unroll
        for (int q = 0; q < 4; q++) v[q] = ldg4(b1r + q * 4);
#pragma unroll
        for (int i = 0; i < 8; i++) {
            float s = h0[i];
#pragma unroll
            for (int q = 0; q < 4; q++) fma4(v[q], s, ldg4(w1r + i * 16 + q * 4));
        }
#pragma unroll
        for (int q = 0; q < 4; q++) g_xr1[n * 4 + q] = v[q];
    }
}

// ---------------- edge pass, layer 1 (4 threads/edge; packs edge data) -----
__global__ void k_edge1(const int* __restrict__ ei, const float* __restrict__ ew,
                        const float* __restrict__ ce,
                        const float* __restrict__ w1e, const float* __restrict__ att1,
                        int E) {
    int t = blockIdx.x * blockDim.x + threadIdx.x;
    int e = t >> 2, h = t & 3;
    if (e >= E) return;
    int s = __ldg(ei + e);
    int d = __ldg(ei + (size_t)E + e);
    float w = __ldg(ew + e), c = __ldg(ce + e);
    if (h == 0) {
        g_ep[e] = make_float4(__int_as_float(s), __int_as_float(d), w, c);
        redAdd4(&g_lc[d], make_float4(w, c, 1.f, 0.f));
    }
    float4 xl = __ldg(&g_xl1[s * 4 + h]);
    float4 xr = __ldg(&g_xr1[d * 4 + h]);
    float4 wa = ldg4(&w1e[h * 4]);
    float4 wb = ldg4(&w1e[16 + h * 4]);
    float4 at = ldg4(&att1[h * 4]);
    float4 m;
    m.x = xl.x + xr.x + w * wa.x + c * wb.x;
    m.y = xl.y + xr.y + w * wa.y + c * wb.y;
    m.z = xl.z + xr.z + w * wa.z + c * wb.z;
    m.w = xl.w + xr.w + w * wa.w + c * wb.w;
    float al = dot4(lrelu4(m), at);
    float ex = __expf(al);
    redAdd(&g_den1[d * 4 + h], ex);
    redAdd4(&g_acc1[d * 4 + h], make_float4(ex * xl.x, ex * xl.y, ex * xl.z, ex * xl.w));
}

// ---------------- node: self-loop + normalize layer1 + layer2 projections --
__global__ void __launch_bounds__(128, 6) k_selfnorm1(
    const float* __restrict__ w1e, const float* __restrict__ att1,
    const float* __restrict__ bias1,
    const float* __restrict__ w2l, const float* __restrict__ b2l,
    const float* __restrict__ w2r, const float* __restrict__ b2r, int N)
{
    int n = blockIdx.x * blockDim.x + threadIdx.x;
    if (n >= N) return;
    float4 lc = g_lc[n];
    float icnt = __fdividef(1.f, fmaxf(lc.z, 1.f));
    float la0 = lc.x * icnt, la1 = lc.y * icnt;
    float h1[16];
#pragma unroll
    for (int h = 0; h < 4; h++) {
        float4 xl = g_xl1[n * 4 + h];
        float4 xr = g_xr1[n * 4 + h];
        float4 wa = ldg4(&w1e[h * 4]);
        float4 wb = ldg4(&w1e[16 + h * 4]);
        float4 at = ldg4(&att1[h * 4]);
        float4 m;
        m.x = xl.x + xr.x + la0 * wa.x + la1 * wb.x;
        m.y = xl.y + xr.y + la0 * wa.y + la1 * wb.y;
        m.z = xl.z + xr.z + la0 * wa.z + la1 * wb.z;
        m.w = xl.w + xr.w + la0 * wa.w + la1 * wb.w;
        float ex = __expf(dot4(lrelu4(m), at));
        float iden = __fdividef(1.f, g_den1[n * 4 + h] + ex);
        float4 ac = g_acc1[n * 4 + h];
        float4 bi = ldg4(&bias1[h * 4]);
        h1[h * 4 + 0] = fmaxf((ac.x + ex * xl.x) * iden + bi.x, 0.f);
        h1[h * 4 + 1] = fmaxf((ac.y + ex * xl.y) * iden + bi.y, 0.f);
        h1[h * 4 + 2] = fmaxf((ac.z + ex * xl.z) * iden + bi.z, 0.f);
        h1[h * 4 + 3] = fmaxf((ac.w + ex * xl.w) * iden + bi.w, 0.f);
    }
    {
        float4 v[8];
#pragma unroll
        for (int q = 0; q < 8; q++) v[q] = ldg4(b2l + q * 4);
#pragma unroll
        for (int i = 0; i < 16; i++) {
            float s = h1[i];
#pragma unroll
            for (int q = 0; q < 8; q++) fma4(v[q], s, ldg4(w2l + i * 32 + q * 4));
        }
#pragma unroll
        for (int q = 0; q < 8; q++) g_xl2[n * 8 + q] = v[q];
    }
    {
        float4 v[8];
#pragma unroll
        for (int q = 0; q < 8; q++) v[q] = ldg4(b2r + q * 4);
#pragma unroll
        for (int i = 0; i < 16; i++) {
            float s = h1[i];
#pragma unroll
            for (int q = 0; q < 8; q++) fma4(v[q], s, ldg4(w2r + i * 32 + q * 4));
        }
#pragma unroll
        for (int q = 0; q < 8; q++) g_xr2[n * 8 + q] = v[q];
    }
}

// ---------------- edge pass, layer 2 (8 lanes x 2 edges; packed data) ------
__global__ void k_edge2(const float* __restrict__ w2e, const float* __restrict__ att2,
                        int E) {
    long long t = (long long)blockIdx.x * blockDim.x + threadIdx.x;
    int pair = (int)(t >> 3);
    int sub = (int)(t & 7);
    int h = sub >> 1, half = sub & 1;
    // weights shared across both edges of the pair (hoisted out of the loop)
    float4 wa = ldg4(&w2e[h * 8 + half * 4]);
    float4 wb = ldg4(&w2e[32 + h * 8 + half * 4]);
    float4 at = ldg4(&att2[h * 8 + half * 4]);
#pragma unroll
    for (int k = 0; k < 2; k++) {
        int e = pair * 2 + k;
        bool valid = (e < E);
        int ec = valid ? e : 0;
        float4 ep = __ldg(&g_ep[ec]);
        int s = __float_as_int(ep.x);
        int d = __float_as_int(ep.y);
        float w = ep.z, c = ep.w;
        float4 a = __ldg(&g_xl2[s * 8 + h * 2 + half]);
        float4 b = __ldg(&g_xr2[d * 8 + h * 2 + half]);
        float4 m;
        m.x = a.x + b.x + w * wa.x + c * wb.x;
        m.y = a.y + b.y + w * wa.y + c * wb.y;
        m.z = a.z + b.z + w * wa.z + c * wb.z;
        m.w = a.w + b.w + w * wa.w + c * wb.w;
        float part = dot4(lrelu4(m), at);
        float al = part + __shfl_xor_sync(0xffffffffu, part, 1);
        float ex = __expf(al);
        if (valid) {
            redAdd4(&g_acc2[d * 8 + h * 2 + half],
                    make_float4(ex * a.x, ex * a.y, ex * a.z, ex * a.w));
            if (half == 0) redAdd(&g_den2[d * 4 + h], ex);
        }
    }
}

// ---------------- node: self-loop + normalize layer2 + FC + ps/pd ----------
__global__ void __launch_bounds__(128, 6) k_selfnorm2(
    const float* __restrict__ w2e, const float* __restrict__ att2,
    const float* __restrict__ bias2,
    const float* __restrict__ wfc, const float* __restrict__ bfc, int N)
{
    int n = blockIdx.x * blockDim.x + threadIdx.x;
    if (n >= N) return;
    float4 lc = g_lc[n];
    float icnt = __fdividef(1.f, fmaxf(lc.z, 1.f));
    float la0 = lc.x * icnt, la1 = lc.y * icnt;
    float h2[32];
#pragma unroll
    for (int h = 0; h < 4; h++) {
        float4 a0 = g_xl2[n * 8 + h * 2], a1 = g_xl2[n * 8 + h * 2 + 1];
        float4 b0 = g_xr2[n * 8 + h * 2], b1 = g_xr2[n * 8 + h * 2 + 1];
        float4 wa0 = ldg4(&w2e[h * 8]),      wa1 = ldg4(&w2e[h * 8 + 4]);
        float4 wb0 = ldg4(&w2e[32 + h * 8]), wb1 = ldg4(&w2e[32 + h * 8 + 4]);
        float4 at0 = ldg4(&att2[h * 8]),     at1 = ldg4(&att2[h * 8 + 4]);
        float4 m0, m1;
        m0.x = a0.x + b0.x + la0 * wa0.x + la1 * wb0.x;
        m0.y = a0.y + b0.y + la0 * wa0.y + la1 * wb0.y;
        m0.z = a0.z + b0.z + la0 * wa0.z + la1 * wb0.z;
        m0.w = a0.w + b0.w + la0 * wa0.w + la1 * wb0.w;
        m1.x = a1.x + b1.x + la0 * wa1.x + la1 * wb1.x;
        m1.y = a1.y + b1.y + la0 * wa1.y + la1 * wb1.y;
        m1.z = a1.z + b1.z + la0 * wa1.z + la1 * wb1.z;
        m1.w = a1.w + b1.w + la0 * wa1.w + la1 * wb1.w;
        float ex = __expf(dot4(lrelu4(m0), at0) + dot4(lrelu4(m1), at1));
        float iden = __fdividef(1.f, g_den2[n * 4 + h] + ex);
        float4 c0 = g_acc2[n * 8 + h * 2], c1 = g_acc2[n * 8 + h * 2 + 1];
        float4 bi0 = ldg4(&bias2[h * 8]), bi1 = ldg4(&bias2[h * 8 + 4]);
        h2[h * 8 + 0] = fmaxf((c0.x + ex * a0.x) * iden + bi0.x, 0.f);
        h2[h * 8 + 1] = fmaxf((c0.y + ex * a0.y) * iden + bi0.y, 0.f);
        h2[h * 8 + 2] = fmaxf((c0.z + ex * a0.z) * iden + bi0.z, 0.f);
        h2[h * 8 + 3] = fmaxf((c0.w + ex * a0.w) * iden + bi0.w, 0.f);
        h2[h * 8 + 4] = fmaxf((c1.x + ex * a1.x) * iden + bi1.x, 0.f);
        h2[h * 8 + 5] = fmaxf((c1.y + ex * a1.y) * iden + bi1.y, 0.f);
        h2[h * 8 + 6] = fmaxf((c1.z + ex * a1.z) * iden + bi1.z, 0.f);
        h2[h * 8 + 7] = fmaxf((c1.w + ex * a1.w) * iden + bi1.w, 0.f);
    }
    float p0 = 0.f, p1 = 0.f, q0 = 0.f, q1 = 0.f;
#pragma unroll
    for (int half = 0; half < 2; half++) {
        float4 acc[4];
#pragma unroll
        for (int q = 0; q < 4; q++) acc[q] = ldg4(bfc + half * 16 + q * 4);
#pragma unroll
        for (int i = 0; i < 32; i++) {
            float v = h2[i];
#pragma unroll
            for (int q = 0; q < 4; q++)
                fma4(acc[q], v, ldg4(wfc + i * 32 + half * 16 + q * 4));
        }
#pragma unroll
        for (int q = 0; q < 4; q++) {
            float hv[4] = {fmaxf(acc[q].x, 0.f), fmaxf(acc[q].y, 0.f),
                           fmaxf(acc[q].z, 0.f), fmaxf(acc[q].w, 0.f)};
#pragma unroll
            for (int cmp = 0; cmp < 4; cmp++) {
                int k = half * 16 + q * 4 + cmp;
                float4 wp = ldg4(&g_Wp[k * 4]);
                p0 += hv[cmp] * wp.x; p1 += hv[cmp] * wp.y;
                q0 += hv[cmp] * wp.z; q1 += hv[cmp] * wp.w;
            }
        }
    }
    g_ps[n] = make_float2(p0, p1);
    g_pd[n] = make_float2(q0, q1);
}

// ---------------- final edge output (packed edge data) ----------------
__global__ void k_edgeout(float* __restrict__ out, int E) {
    int e = blockIdx.x * blockDim.x + threadIdx.x;
    if (e >= E) return;
    float4 ep = __ldg(&g_ep[e]);
    int s = __float_as_int(ep.x);
    int d = __float_as_int(ep.y);
    float2 ps = __ldg(&g_ps[s]);
    float2 pd = __ldg(&g_pd[d]);
    float2 o;
    o.x = __ldg(&g_Wb[0]) + ep.z * __ldg(&g_W[0]) + ep.w * __ldg(&g_W[2]) + ps.x + pd.x;
    o.y = __ldg(&g_Wb[1]) + ep.z * __ldg(&g_W[1]) + ep.w * __ldg(&g_W[3]) + ps.y + pd.y;
    __stcs((float2*)out + e, o);   // streaming store: output never re-read
}

// ---------------- launch ----------------
extern "C" void kernel_launch(void* const* d_in, const int* in_sizes, int n_in,
                              void* d_out, int out_size) {
    const float* x  = (const float*)d_in[0];
    const int*   ei = (const int*)d_in[1];   // int32 [2,E]
    const float* ew = (const float*)d_in[2];
    const float* ce = (const float*)d_in[3];
    int N = in_sizes[0] / 5;
    int E = in_sizes[2];

    const float* w_init = (const float*)d_in[4];
    const float* b_init = (const float*)d_in[5];
    const float* w1l = (const float*)d_in[6];
    const float* b1l = (const float*)d_in[7];
    const float* w1r = (const float*)d_in[8];
    const float* b1r = (const float*)d_in[9];
    const float* w1e = (const float*)d_in[10];
    const float* att1 = (const float*)d_in[11];
    const float* bias1 = (const float*)d_in[12];
    const float* w2l = (const float*)d_in[13];
    const float* b2l = (const float*)d_in[14];
    const float* w2r = (const float*)d_in[15];
    const float* b2r = (const float*)d_in[16];
    const float* w2e = (const float*)d_in[17];
    const float* att2 = (const float*)d_in[18];
    const float* bias2 = (const float*)d_in[19];
    const float* wfc = (const float*)d_in[20];
    const float* bfc = (const float*)d_in[21];
    const float* we1 = (const float*)d_in[22];
    const float* be1 = (const float*)d_in[23];
    const float* we2 = (const float*)d_in[24];
    const float* be2 = (const float*)d_in[25];

    int nb = (N + 127) / 128;
    k_nodes1<<<nb, 128>>>(x, w_init, b_init, w1l, b1l, w1r, b1r,
                          we1, be1, we2, be2, N);

    long long tE4 = 4LL * E;
    int eb4 = (int)((tE4 + 255) / 256);
    k_edge1<<<eb4, 256>>>(ei, ew, ce, w1e, att1, E);
    k_selfnorm1<<<nb, 128>>>(w1e, att1, bias1, w2l, b2l, w2r, b2r, N);

    // 8 lanes per edge-pair: threads = 8 * ceil(E/2) = 4*E (E even)
    long long tP = 8LL * ((E + 1) / 2);
    int ebP = (int)((tP + 255) / 256);
    k_edge2<<<ebP, 256>>>(w2e, att2, E);
    k_selfnorm2<<<nb, 128>>>(w2e, att2, bias2, wfc, bfc, N);
    k_edgeout<<<(E + 255) / 256, 256>>>((float*)d_out, E);
}